// round 8
// baseline (speedup 1.0000x reference)
#include <cuda_runtime.h>
#include <cuda_bf16.h>

// x:    (b=8, t=50, f=129, c1=32, c2=32) float32
// mask: (g=8, f=129) float32
// out:  (b=8, t=50, g=8, c1=32, c2=32) float32
//
// out[b,t,g,:,:] = sum_{f in band g} x[b,t,f,:,:] / count[g]
//
// DRAM-BW-bound streaming (~211 MB read + 13 MB write), measured ceiling
// ~6 TB/s. One CTA per (b,t, band-pair), grid = 1600. This round both bands
// of a pair are processed by ONE fused MLP-8 load loop (address + accumulator
// selected per-k by predicate), so the CTA issues loads continuously with a
// single accumulator drain instead of two serialized band loops.

#define N_F      129
#define N_BANDS  8
#define PIX4     256        // 32*32 pixels / 4 floats

__global__ __launch_bounds__(256, 4) void band_avg_kernel(
    const float* __restrict__ x,
    const float* __restrict__ masks,
    float* __restrict__ out)
{
    __shared__ unsigned bits[2][5];        // ballot bitmap per band
    __shared__ int   s_start[2], s_cnt[2], s_contig[2];
    __shared__ float s_inv[2];

    const int tid = threadIdx.x;
    const int bid = blockIdx.x;            // 0..1599
    const int gp  = bid & 3;               // pair id 0..3
    const int bt  = bid >> 2;              // (b,t) tile 0..399
    const int g0  = gp;
    const int g1  = (N_BANDS - 1) - gp;

    // --- parallel mask compaction for both bands (warps 0..4) ---
    const int wid = tid >> 5;
    if (wid < 5) {
        bool on0 = false, on1 = false;
        if (tid < N_F) {
            on0 = (masks[g0 * N_F + tid] > 0.5f);
            on1 = (masks[g1 * N_F + tid] > 0.5f);
        }
        unsigned b0 = __ballot_sync(0xffffffffu, on0);
        unsigned b1 = __ballot_sync(0xffffffffu, on1);
        if ((tid & 31) == 0) { bits[0][wid] = b0; bits[1][wid] = b1; }
    }
    __syncthreads();

    if (tid < 2) {
        int total = 0, first = -1, last = -1;
        #pragma unroll
        for (int w = 0; w < 5; ++w) {
            unsigned b = bits[tid][w];
            total += __popc(b);
            if (b) {
                if (first < 0) first = w * 32 + __ffs(b) - 1;
                last = w * 32 + 31 - __clz(b);
            }
        }
        s_start[tid]  = first;
        s_cnt[tid]    = total;
        s_contig[tid] = (last - first + 1 == total) ? 1 : 0;
        s_inv[tid]    = 1.0f / (float)total;
    }
    __syncthreads();

    const float4* __restrict__ xin =
        reinterpret_cast<const float4*>(x) + ((size_t)bt * (N_F * PIX4) + tid);
    float4* __restrict__ o4 =
        reinterpret_cast<float4*>(out) + ((size_t)bt * (N_BANDS * PIX4) + tid);

    if (s_contig[0] && s_contig[1]) {
        const int c0 = s_cnt[0];
        const int c1 = s_cnt[1];
        const int cc = c0 + c1;
        // Per-k float4 index into this tile: band0 bins then band1 bins,
        // one continuous load stream.
        const int base0 = s_start[0] * PIX4;
        const int base1 = (s_start[1] - c0) * PIX4;   // so idx = base1 + k*PIX4

        float a0x = 0.f, a0y = 0.f, a0z = 0.f, a0w = 0.f;   // band 0 sums
        float a1x = 0.f, a1y = 0.f, a1z = 0.f, a1w = 0.f;   // band 1 sums

        int k = 0;
        #pragma unroll 1
        for (; k + 8 <= cc; k += 8) {
            float4 v[8];
            bool   b0[8];
            #pragma unroll
            for (int j = 0; j < 8; ++j) {
                const int kk  = k + j;
                b0[j] = (kk < c0);
                const int idx = (b0[j] ? base0 : base1) + kk * PIX4;
                v[j] = __ldcs(&xin[idx]);
            }
            #pragma unroll
            for (int j = 0; j < 8; ++j) {
                if (b0[j]) { a0x += v[j].x; a0y += v[j].y; a0z += v[j].z; a0w += v[j].w; }
                else       { a1x += v[j].x; a1y += v[j].y; a1z += v[j].z; a1w += v[j].w; }
            }
        }
        #pragma unroll 1
        for (; k < cc; ++k) {
            const bool in0 = (k < c0);
            const int idx  = (in0 ? base0 : base1) + k * PIX4;
            float4 v = __ldcs(&xin[idx]);
            if (in0) { a0x += v.x; a0y += v.y; a0z += v.z; a0w += v.w; }
            else     { a1x += v.x; a1y += v.y; a1z += v.z; a1w += v.w; }
        }

        float4 r0, r1;
        const float i0 = s_inv[0], i1 = s_inv[1];
        r0.x = a0x * i0; r0.y = a0y * i0; r0.z = a0z * i0; r0.w = a0w * i0;
        r1.x = a1x * i1; r1.y = a1y * i1; r1.z = a1z * i1; r1.w = a1w * i1;
        o4[g0 * PIX4] = r0;
        o4[g1 * PIX4] = r1;
    } else {
        // generic fallback: iterate the bitmaps (unused for reference mask)
        #pragma unroll 1
        for (int s = 0; s < 2; ++s) {
            const int g = s ? g1 : g0;
            float ax = 0.f, ay = 0.f, az = 0.f, aw = 0.f;
            #pragma unroll 1
            for (int f = 0; f < N_F; ++f) {
                if ((bits[s][f >> 5] >> (f & 31)) & 1u) {
                    float4 v = __ldcs(&xin[f * PIX4]);
                    ax += v.x; ay += v.y; az += v.z; aw += v.w;
                }
            }
            float4 r;
            const float inv = s_inv[s];
            r.x = ax * inv; r.y = ay * inv; r.z = az * inv; r.w = aw * inv;
            o4[g * PIX4] = r;
        }
    }
}

extern "C" void kernel_launch(void* const* d_in, const int* in_sizes, int n_in,
                              void* d_out, int out_size)
{
    const float* x     = (const float*)d_in[0];
    const float* masks = (const float*)d_in[1];
    if (n_in >= 2 && in_sizes[0] < in_sizes[1]) {
        x     = (const float*)d_in[1];
        masks = (const float*)d_in[0];
    }
    float* out = (float*)d_out;

    const int n_blocks = 8 * 50 * (N_BANDS / 2);  // 1600: one per (b,t,pair)
    band_avg_kernel<<<n_blocks, 256>>>(x, masks, out);
}